// round 1
// baseline (speedup 1.0000x reference)
#include <cuda_runtime.h>
#include <cuda_bf16.h>
#include <cstdint>

// Problem constants (fixed shapes for this problem instance)
#define NC_MAX 1000000
#define NP_MAX 100000
#define DIM 64
#define H 4
#define DQK 8
#define DH 32
#define RPE 9
#define KVW 96
#define SCALE 0.35355339059327373f  // 8^-0.5

// ---------------- device scratch (no allocations allowed) ----------------
__device__ __align__(16) float g_qp[NP_MAX * DH];     // prescaled parent q (incl bq, *SCALE)
__device__ __align__(16) float g_e[NC_MAX * H];       // exp(compat) per child/head
__device__ __align__(16) float g_s[NP_MAX * H];       // segment sums
__device__ __align__(16) float g_sinv[NP_MAX * H];    // 1/(s+1e-16)
__device__ int g_idx[NC_MAX];                         // index as int32
__device__ int g_is64;                                // 1 if index dtype is int64

// ---------------- index dtype detection ----------------
// JAX without x64 silently turns the declared int64 index into int32.
// If the raw buffer is int64 (little-endian, values in [0, 1e5)), every odd
// 32-bit word is zero. If it is int32, odd words are random parent ids and
// the chance all 2048 sampled words are zero is ~0.
__global__ void detect_kernel(const unsigned int* __restrict__ raw, int nc) {
    __shared__ int found;
    if (threadIdx.x == 0) found = 0;
    __syncthreads();
    int limit = nc / 2; if (limit > 2048) limit = 2048;
    for (int i = threadIdx.x; i < limit; i += blockDim.x)
        if (raw[2 * i + 1] != 0u) found = 1;
    __syncthreads();
    if (threadIdx.x == 0) g_is64 = (found == 0) ? 1 : 0;
}

__global__ void cvt_index_kernel(const void* __restrict__ idxp, int nc) {
    int i = blockIdx.x * blockDim.x + threadIdx.x;
    if (i >= nc) return;
    if (g_is64) g_idx[i] = (int)((const long long*)idxp)[i];
    else        g_idx[i] = ((const int*)idxp)[i];
}

// ---------------- parent query projection ----------------
// One warp per parent; lane t owns output column t; wq column in 64 registers.
__global__ void __launch_bounds__(256, 2) qp_kernel(
    const float* __restrict__ x_parent, const float* __restrict__ wq,
    const float* __restrict__ bq, int np)
{
    const int t = threadIdx.x & 31;
    const int w = threadIdx.x >> 5;
    __shared__ __align__(16) float xs[8][64];

    float wr[64];
#pragma unroll
    for (int c = 0; c < 64; c++) wr[c] = wq[c * DH + t];
    const float b = bq[t];

    const int warps_total = gridDim.x * 8;
    for (int p = blockIdx.x * 8 + w; p < np; p += warps_total) {
        size_t base = (size_t)p * DIM;
        xs[w][t]      = x_parent[base + t];
        xs[w][t + 32] = x_parent[base + 32 + t];
        __syncwarp();
        float a0 = b, a1 = 0.f, a2 = 0.f, a3 = 0.f;
#pragma unroll
        for (int c = 0; c < 64; c += 4) {
            float4 xv = *(const float4*)&xs[w][c];
            a0 += xv.x * wr[c];
            a1 += xv.y * wr[c + 1];
            a2 += xv.z * wr[c + 2];
            a3 += xv.w * wr[c + 3];
        }
        g_qp[(size_t)p * DH + t] = ((a0 + a1) + (a2 + a3)) * SCALE;
        __syncwarp();
    }
}

// ---------------- compat + exp + segment-sum pass ----------------
// One warp per child; lane t owns k/q column t. Wk column + both RPE columns
// live in registers (persistent grid-stride loop amortizes the load).
__global__ void __launch_bounds__(256, 2) compat_kernel(
    const float* __restrict__ x_child, const float* __restrict__ edge_attr,
    const float* __restrict__ wkv, const float* __restrict__ bkv,
    const float* __restrict__ wk_rpe, const float* __restrict__ bk_rpe,
    const float* __restrict__ wq_rpe, const float* __restrict__ bq_rpe,
    int nc)
{
    const int t = threadIdx.x & 31;
    const int w = threadIdx.x >> 5;
    __shared__ __align__(16) float xs[8][64];
    __shared__ float es[8][12];

    float wk[64];
#pragma unroll
    for (int c = 0; c < 64; c++) wk[c] = wkv[c * KVW + t];
    float wkr[RPE], wqr[RPE];
#pragma unroll
    for (int r = 0; r < RPE; r++) {
        wkr[r] = wk_rpe[r * DH + t];
        wqr[r] = wq_rpe[r * DH + t];
    }
    const float bk = bkv[t] + bk_rpe[t];
    const float bqr = bq_rpe[t];

    const int warps_total = gridDim.x * 8;
    for (int i = blockIdx.x * 8 + w; i < nc; i += warps_total) {
        size_t base = (size_t)i * DIM;
        xs[w][t]      = x_child[base + t];
        xs[w][t + 32] = x_child[base + 32 + t];
        if (t < RPE) es[w][t] = edge_attr[(size_t)i * RPE + t];
        const int p = g_idx[i];
        float q = g_qp[(size_t)p * DH + t] + bqr;
        __syncwarp();

        float a0 = bk, a1 = 0.f, a2 = 0.f, a3 = 0.f;
#pragma unroll
        for (int c = 0; c < 64; c += 4) {
            float4 xv = *(const float4*)&xs[w][c];
            a0 += xv.x * wk[c];
            a1 += xv.y * wk[c + 1];
            a2 += xv.z * wk[c + 2];
            a3 += xv.w * wk[c + 3];
        }
        float k = (a0 + a1) + (a2 + a3);
#pragma unroll
        for (int r = 0; r < RPE; r++) {
            float e = es[w][r];
            k += e * wkr[r];
            q += e * wqr[r];
        }
        float pv = q * k;
        pv += __shfl_xor_sync(0xffffffffu, pv, 1);
        pv += __shfl_xor_sync(0xffffffffu, pv, 2);
        pv += __shfl_xor_sync(0xffffffffu, pv, 4);
        float e = expf(pv);  // max-subtraction dropped: compat has tiny magnitude

        float e0 = __shfl_sync(0xffffffffu, e, 0);
        float e1 = __shfl_sync(0xffffffffu, e, 8);
        float e2 = __shfl_sync(0xffffffffu, e, 16);
        float e3 = __shfl_sync(0xffffffffu, e, 24);
        if (t == 0) {
            *(float4*)&g_e[(size_t)i * H] = make_float4(e0, e1, e2, e3);
            asm volatile("red.global.add.v4.f32 [%0], {%1,%2,%3,%4};"
                         :: "l"(g_s + (size_t)p * H),
                            "f"(e0), "f"(e1), "f"(e2), "f"(e3) : "memory");
        }
        __syncwarp();
    }
}

// ---------------- segment-sum reciprocal ----------------
__global__ void sinv_kernel(int n) {
    int i = blockIdx.x * blockDim.x + threadIdx.x;
    if (i < n) g_sinv[i] = 1.0f / (g_s[i] + 1e-16f);
}

// ---------------- V projection + attn-weighted scatter ----------------
// 64 threads per block = one child at a time; lane j owns output channel j,
// Wv column in 64 registers. Vectorized v4 reductions into d_out.
__global__ void __launch_bounds__(64, 10) vout_kernel(
    const float* __restrict__ x_child, const float* __restrict__ wkv,
    const float* __restrict__ bkv, float* __restrict__ out, int nc)
{
    const int j = threadIdx.x;  // 0..63
    __shared__ __align__(16) float xs[64];
    __shared__ __align__(16) float vs[64];

    float wv[64];
#pragma unroll
    for (int c = 0; c < 64; c++) wv[c] = wkv[c * KVW + DH + j];
    const float bv = bkv[DH + j];
    const int h = j >> 4;

    for (int i = blockIdx.x; i < nc; i += gridDim.x) {
        xs[j] = x_child[(size_t)i * DIM + j];
        __syncthreads();
        float a0 = bv, a1 = 0.f, a2 = 0.f, a3 = 0.f;
#pragma unroll
        for (int c = 0; c < 64; c += 4) {
            float4 xv = *(const float4*)&xs[c];
            a0 += xv.x * wv[c];
            a1 += xv.y * wv[c + 1];
            a2 += xv.z * wv[c + 2];
            a3 += xv.w * wv[c + 3];
        }
        float v = (a0 + a1) + (a2 + a3);
        const int p = g_idx[i];
        float attn = g_e[(size_t)i * H + h] * g_sinv[(size_t)p * H + h];
        vs[j] = v * attn;
        __syncthreads();
        if (j < 16) {
            float4 r = *(const float4*)&vs[j * 4];
            asm volatile("red.global.add.v4.f32 [%0], {%1,%2,%3,%4};"
                         :: "l"(out + (size_t)p * DIM + j * 4),
                            "f"(r.x), "f"(r.y), "f"(r.z), "f"(r.w) : "memory");
        }
    }
}

// ---------------- launch ----------------
extern "C" void kernel_launch(void* const* d_in, const int* in_sizes, int n_in,
                              void* d_out, int out_size) {
    const float* x_child   = (const float*)d_in[0];
    const float* x_parent  = (const float*)d_in[1];
    const void*  index     = d_in[2];
    const float* edge_attr = (const float*)d_in[3];
    const float* wq        = (const float*)d_in[4];
    const float* bq        = (const float*)d_in[5];
    const float* wkv       = (const float*)d_in[6];
    const float* bkv       = (const float*)d_in[7];
    const float* wk_rpe    = (const float*)d_in[8];
    const float* bk_rpe    = (const float*)d_in[9];
    const float* wq_rpe    = (const float*)d_in[10];
    const float* bq_rpe    = (const float*)d_in[11];
    float* out = (float*)d_out;

    const int nc = in_sizes[0] / DIM;
    const int np = in_sizes[1] / DIM;

    // zero accumulators (out is poisoned to 0xAA by the harness)
    cudaMemsetAsync(d_out, 0, (size_t)out_size * sizeof(float));
    void* s_addr = nullptr;
    cudaGetSymbolAddress(&s_addr, g_s);
    cudaMemsetAsync(s_addr, 0, (size_t)np * H * sizeof(float));

    detect_kernel<<<1, 256>>>((const unsigned int*)index, nc);
    cvt_index_kernel<<<(nc + 255) / 256, 256>>>(index, nc);

    qp_kernel<<<208, 256>>>(x_parent, wq, bq, np);

    compat_kernel<<<304, 256>>>(x_child, edge_attr, wkv, bkv,
                                wk_rpe, bk_rpe, wq_rpe, bq_rpe, nc);

    sinv_kernel<<<(np * H + 255) / 256, 256>>>(np * H);

    vout_kernel<<<1824, 64>>>(x_child, wkv, bkv, out, nc);
}

// round 2
// speedup vs baseline: 2.2407x; 2.2407x over previous
#include <cuda_runtime.h>
#include <cuda_bf16.h>
#include <cstdint>

#define NC_MAX 1000000
#define NP_MAX 100000
#define DIM 64
#define H 4
#define DQK 8
#define DH 32
#define RPE 9
#define KVW 96
#define SCALE 0.35355339059327373f  // 8^-0.5

// ---------------- device scratch ----------------
__device__ __align__(16) float g_qp[NP_MAX * DH];
__device__ __align__(16) float g_e[NC_MAX * H];
__device__ __align__(16) float g_s[NP_MAX * H];
__device__ __align__(16) float g_sinv[NP_MAX * H];
__device__ int g_idx[NC_MAX];
__device__ int g_is64;

// ---------------- index dtype detection ----------------
__global__ void detect_kernel(const unsigned int* __restrict__ raw, int nc) {
    __shared__ int found;
    if (threadIdx.x == 0) found = 0;
    __syncthreads();
    int limit = nc / 2; if (limit > 2048) limit = 2048;
    for (int i = threadIdx.x; i < limit; i += blockDim.x)
        if (raw[2 * i + 1] != 0u) found = 1;
    __syncthreads();
    if (threadIdx.x == 0) g_is64 = (found == 0) ? 1 : 0;
}

__global__ void cvt_index_kernel(const void* __restrict__ idxp, int nc) {
    int i = blockIdx.x * blockDim.x + threadIdx.x;
    if (i >= nc) return;
    if (g_is64) g_idx[i] = (int)((const long long*)idxp)[i];
    else        g_idx[i] = ((const int*)idxp)[i];
}

// ---------------- parent query projection ----------------
__global__ void __launch_bounds__(256, 2) qp_kernel(
    const float* __restrict__ x_parent, const float* __restrict__ wq,
    const float* __restrict__ bq, int np)
{
    const int t = threadIdx.x & 31;
    const int w = threadIdx.x >> 5;
    __shared__ __align__(16) float xs[8][64];

    float wr[64];
#pragma unroll
    for (int c = 0; c < 64; c++) wr[c] = wq[c * DH + t];
    const float b = bq[t];

    const int warps_total = gridDim.x * 8;
    for (int p = blockIdx.x * 8 + w; p < np; p += warps_total) {
        size_t base = (size_t)p * DIM;
        xs[w][t]      = x_parent[base + t];
        xs[w][t + 32] = x_parent[base + 32 + t];
        __syncwarp();
        float a0 = b, a1 = 0.f, a2 = 0.f, a3 = 0.f;
#pragma unroll
        for (int c = 0; c < 64; c += 4) {
            float4 xv = *(const float4*)&xs[w][c];
            a0 += xv.x * wr[c];
            a1 += xv.y * wr[c + 1];
            a2 += xv.z * wr[c + 2];
            a3 += xv.w * wr[c + 3];
        }
        g_qp[(size_t)p * DH + t] = ((a0 + a1) + (a2 + a3)) * SCALE;
        __syncwarp();
    }
}

// ---------------- compat + exp + segment-sum (prefetch-pipelined) ----------------
__global__ void __launch_bounds__(256, 2) compat_kernel(
    const float* __restrict__ x_child, const float* __restrict__ edge_attr,
    const float* __restrict__ wkv, const float* __restrict__ bkv,
    const float* __restrict__ wk_rpe, const float* __restrict__ bk_rpe,
    const float* __restrict__ wq_rpe, const float* __restrict__ bq_rpe,
    int nc)
{
    const int t = threadIdx.x & 31;
    const int w = threadIdx.x >> 5;
    __shared__ __align__(16) float xs[8][64];
    __shared__ float es[8][12];

    float wk[64];
#pragma unroll
    for (int c = 0; c < 64; c++) wk[c] = wkv[c * KVW + t];
    float wkr[RPE], wqr[RPE];
#pragma unroll
    for (int r = 0; r < RPE; r++) {
        wkr[r] = wk_rpe[r * DH + t];
        wqr[r] = wq_rpe[r * DH + t];
    }
    const float bk = bkv[t] + bk_rpe[t];
    const float bqr = bq_rpe[t];

    const int stride = gridDim.x * 8;
    int i = blockIdx.x * 8 + w;

    // prime the pipeline
    float xlo = 0.f, xhi = 0.f, ea = 0.f, qv = 0.f;
    int p = 0;
    if (i < nc) {
        xlo = x_child[i * 64 + t];
        xhi = x_child[i * 64 + 32 + t];
        if (t < RPE) ea = edge_attr[i * RPE + t];
        p = g_idx[i];
        qv = g_qp[p * DH + t];
    }

    while (i < nc) {
        const int inext = i + stride;
        xs[w][t]      = xlo;
        xs[w][t + 32] = xhi;
        if (t < RPE) es[w][t] = ea;
        const float q0 = qv + bqr;
        const int pcur = p;
        __syncwarp();

        // prefetch next child (hides gather-chain latency under compute)
        float nxlo = 0.f, nxhi = 0.f, nea = 0.f, nqv = 0.f;
        int pn = 0;
        if (inext < nc) {
            nxlo = x_child[inext * 64 + t];
            nxhi = x_child[inext * 64 + 32 + t];
            if (t < RPE) nea = edge_attr[inext * RPE + t];
            pn = g_idx[inext];
            nqv = g_qp[pn * DH + t];
        }

        float a0 = bk, a1 = 0.f, a2 = 0.f, a3 = 0.f;
#pragma unroll
        for (int c = 0; c < 64; c += 4) {
            float4 xv = *(const float4*)&xs[w][c];
            a0 += xv.x * wk[c];
            a1 += xv.y * wk[c + 1];
            a2 += xv.z * wk[c + 2];
            a3 += xv.w * wk[c + 3];
        }
        float k = (a0 + a1) + (a2 + a3);
        float q = q0;
#pragma unroll
        for (int r = 0; r < RPE; r++) {
            float e = es[w][r];
            k += e * wkr[r];
            q += e * wqr[r];
        }
        float pv = q * k;
        pv += __shfl_xor_sync(0xffffffffu, pv, 1);
        pv += __shfl_xor_sync(0xffffffffu, pv, 2);
        pv += __shfl_xor_sync(0xffffffffu, pv, 4);
        float e = __expf(pv);

        float e0 = __shfl_sync(0xffffffffu, e, 0);
        float e1 = __shfl_sync(0xffffffffu, e, 8);
        float e2 = __shfl_sync(0xffffffffu, e, 16);
        float e3 = __shfl_sync(0xffffffffu, e, 24);
        if (t == 0) {
            *(float4*)&g_e[(size_t)i * H] = make_float4(e0, e1, e2, e3);
            asm volatile("red.global.add.v4.f32 [%0], {%1,%2,%3,%4};"
                         :: "l"(g_s + (size_t)pcur * H),
                            "f"(e0), "f"(e1), "f"(e2), "f"(e3) : "memory");
        }
        __syncwarp();
        i = inext; xlo = nxlo; xhi = nxhi; ea = nea; p = pn; qv = nqv;
    }
}

// ---------------- segment-sum reciprocal ----------------
__global__ void sinv_kernel(int n) {
    int i = blockIdx.x * blockDim.x + threadIdx.x;
    if (i < n) g_sinv[i] = 1.0f / (g_s[i] + 1e-16f);
}

// ---------------- V projection + scatter: tiled register-blocked GEMM ----------------
// Persistent blocks. Tile = 64 children x 64 channels, 256 threads, each thread
// computes a 4x4 micro-tile (16 FFMA per k-step). Weights loaded to shared once
// per block; x tile staged per tile; attn-scaled result staged and scattered
// with red.global.add.v4.
__global__ void __launch_bounds__(256, 4) vout_kernel(
    const float* __restrict__ x_child, const float* __restrict__ wkv,
    const float* __restrict__ bkv, float* __restrict__ out,
    int nc, int ntiles)
{
    __shared__ __align__(16) float ws[64][64];     // ws[c][j]
    __shared__ __align__(16) float xs[64][64];     // xs[child][c]; reused for v output
    __shared__ float attn_s[H][64];                // [h][child]
    __shared__ int   pidx_s[64];

    const int tid = threadIdx.x;
    const int chgrp = tid & 15;          // channel group: channels chgrp*4 .. +3
    const int cbase = (tid >> 4) << 2;   // child base: children cbase .. +3
    const int hh = chgrp >> 2;           // head of this thread's 4 channels

    // load weight tile once (V part of wkv: columns 32..95)
    for (int k = tid; k < 64 * 64; k += 256) {
        int c = k >> 6, j = k & 63;
        ws[c][j] = wkv[c * KVW + DH + j];
    }
    const float4 bvv = *(const float4*)&bkv[DH + chgrp * 4];
    __syncthreads();

    for (int tile = blockIdx.x; tile < ntiles; tile += gridDim.x) {
        const int i0 = tile * 64;

        // stage attn for this tile: 256 threads -> (child, head)
        {
            int child = tid & 63, h = tid >> 6;
            int i = i0 + child;
            float at = 0.f; int p = 0;
            if (i < nc) {
                p = g_idx[i];
                at = g_e[(size_t)i * H + h] * g_sinv[(size_t)p * H + h];
            }
            attn_s[h][child] = at;
            if (h == 0) pidx_s[child] = p;
        }
        // stage x tile: 4 float4 per thread, coalesced
#pragma unroll
        for (int k = 0; k < 4; k++) {
            int idx = tid + 256 * k;         // 0..1023
            int child = idx >> 4, c4 = idx & 15;
            int i = i0 + child;
            float4 xv = make_float4(0.f, 0.f, 0.f, 0.f);
            if (i < nc) xv = *(const float4*)&x_child[(size_t)i * DIM + c4 * 4];
            *(float4*)&xs[child][c4 * 4] = xv;
        }
        __syncthreads();

        // compute 4x4 micro-tile
        float4 a0 = bvv, a1 = bvv, a2 = bvv, a3 = bvv;
#pragma unroll
        for (int c = 0; c < 64; c++) {
            float4 wv = *(const float4*)&ws[c][chgrp * 4];
            float x0 = xs[cbase + 0][c];
            float x1 = xs[cbase + 1][c];
            float x2 = xs[cbase + 2][c];
            float x3 = xs[cbase + 3][c];
            a0.x += x0 * wv.x; a0.y += x0 * wv.y; a0.z += x0 * wv.z; a0.w += x0 * wv.w;
            a1.x += x1 * wv.x; a1.y += x1 * wv.y; a1.z += x1 * wv.z; a1.w += x1 * wv.w;
            a2.x += x2 * wv.x; a2.y += x2 * wv.y; a2.z += x2 * wv.z; a2.w += x2 * wv.w;
            a3.x += x3 * wv.x; a3.y += x3 * wv.y; a3.z += x3 * wv.z; a3.w += x3 * wv.w;
        }
        __syncthreads();   // xs reads done; attn_s visible

        // apply attn, stage v into xs
        {
            float at;
            at = attn_s[hh][cbase + 0];
            a0.x *= at; a0.y *= at; a0.z *= at; a0.w *= at;
            *(float4*)&xs[cbase + 0][chgrp * 4] = a0;
            at = attn_s[hh][cbase + 1];
            a1.x *= at; a1.y *= at; a1.z *= at; a1.w *= at;
            *(float4*)&xs[cbase + 1][chgrp * 4] = a1;
            at = attn_s[hh][cbase + 2];
            a2.x *= at; a2.y *= at; a2.z *= at; a2.w *= at;
            *(float4*)&xs[cbase + 2][chgrp * 4] = a2;
            at = attn_s[hh][cbase + 3];
            a3.x *= at; a3.y *= at; a3.z *= at; a3.w *= at;
            *(float4*)&xs[cbase + 3][chgrp * 4] = a3;
        }
        __syncthreads();

        // scatter: 4 red.v4 per thread
#pragma unroll
        for (int k = 0; k < 4; k++) {
            int idx = tid + 256 * k;
            int child = idx >> 4, grp = idx & 15;
            if (i0 + child < nc) {
                float4 r = *(const float4*)&xs[child][grp * 4];
                asm volatile("red.global.add.v4.f32 [%0], {%1,%2,%3,%4};"
                             :: "l"(out + (size_t)pidx_s[child] * DIM + grp * 4),
                                "f"(r.x), "f"(r.y), "f"(r.z), "f"(r.w) : "memory");
            }
        }
        __syncthreads();   // protect xs/attn_s from next tile's writes
    }
}

// ---------------- launch ----------------
extern "C" void kernel_launch(void* const* d_in, const int* in_sizes, int n_in,
                              void* d_out, int out_size) {
    const float* x_child   = (const float*)d_in[0];
    const float* x_parent  = (const float*)d_in[1];
    const void*  index     = d_in[2];
    const float* edge_attr = (const float*)d_in[3];
    const float* wq        = (const float*)d_in[4];
    const float* bq        = (const float*)d_in[5];
    const float* wkv       = (const float*)d_in[6];
    const float* bkv       = (const float*)d_in[7];
    const float* wk_rpe    = (const float*)d_in[8];
    const float* bk_rpe    = (const float*)d_in[9];
    const float* wq_rpe    = (const float*)d_in[10];
    const float* bq_rpe    = (const float*)d_in[11];
    float* out = (float*)d_out;

    const int nc = in_sizes[0] / DIM;
    const int np = in_sizes[1] / DIM;

    cudaMemsetAsync(d_out, 0, (size_t)out_size * sizeof(float));
    void* s_addr = nullptr;
    cudaGetSymbolAddress(&s_addr, g_s);
    cudaMemsetAsync(s_addr, 0, (size_t)np * H * sizeof(float));

    detect_kernel<<<1, 256>>>((const unsigned int*)index, nc);
    cvt_index_kernel<<<(nc + 255) / 256, 256>>>(index, nc);

    qp_kernel<<<208, 256>>>(x_parent, wq, bq, np);

    compat_kernel<<<296, 256>>>(x_child, edge_attr, wkv, bkv,
                                wk_rpe, bk_rpe, wq_rpe, bq_rpe, nc);

    sinv_kernel<<<(np * H + 255) / 256, 256>>>(np * H);

    const int ntiles = (nc + 63) / 64;
    vout_kernel<<<592, 256>>>(x_child, wkv, bkv, out, nc, ntiles);
}

// round 3
// speedup vs baseline: 2.9274x; 1.3065x over previous
#include <cuda_runtime.h>
#include <cuda_bf16.h>
#include <cstdint>

#define NC_MAX 1000000
#define NP_MAX 100000
#define DIM 64
#define H 4
#define DQK 8
#define DH 32
#define RPE 9
#define KVW 96
#define SCALE 0.35355339059327373f  // 8^-0.5

// ---------------- device scratch ----------------
__device__ __align__(16) float g_qp[NP_MAX * DH];
__device__ __align__(16) float g_e[NC_MAX * H];
__device__ __align__(16) float g_s[NP_MAX * H];
__device__ __align__(16) float g_sinv[NP_MAX * H];
__device__ int g_idx[NC_MAX];
__device__ int g_is64;

// ---------------- index dtype detection ----------------
__global__ void detect_kernel(const unsigned int* __restrict__ raw, int nc) {
    __shared__ int found;
    if (threadIdx.x == 0) found = 0;
    __syncthreads();
    int limit = nc / 2; if (limit > 2048) limit = 2048;
    for (int i = threadIdx.x; i < limit; i += blockDim.x)
        if (raw[2 * i + 1] != 0u) found = 1;
    __syncthreads();
    if (threadIdx.x == 0) g_is64 = (found == 0) ? 1 : 0;
}

__global__ void cvt_index_kernel(const void* __restrict__ idxp, int nc) {
    int i = blockIdx.x * blockDim.x + threadIdx.x;
    if (i >= nc) return;
    if (g_is64) g_idx[i] = (int)((const long long*)idxp)[i];
    else        g_idx[i] = ((const int*)idxp)[i];
}

// ---------------- parent query projection ----------------
__global__ void __launch_bounds__(256, 2) qp_kernel(
    const float* __restrict__ x_parent, const float* __restrict__ wq,
    const float* __restrict__ bq, int np)
{
    const int t = threadIdx.x & 31;
    const int w = threadIdx.x >> 5;
    __shared__ __align__(16) float xs[8][64];

    float wr[64];
#pragma unroll
    for (int c = 0; c < 64; c++) wr[c] = wq[c * DH + t];
    const float b = bq[t];

    const int warps_total = gridDim.x * 8;
    for (int p = blockIdx.x * 8 + w; p < np; p += warps_total) {
        size_t base = (size_t)p * DIM;
        xs[w][t]      = x_parent[base + t];
        xs[w][t + 32] = x_parent[base + 32 + t];
        __syncwarp();
        float a0 = b, a1 = 0.f, a2 = 0.f, a3 = 0.f;
#pragma unroll
        for (int c = 0; c < 64; c += 4) {
            float4 xv = *(const float4*)&xs[w][c];
            a0 += xv.x * wr[c];
            a1 += xv.y * wr[c + 1];
            a2 += xv.z * wr[c + 2];
            a3 += xv.w * wr[c + 3];
        }
        g_qp[(size_t)p * DH + t] = ((a0 + a1) + (a2 + a3)) * SCALE;
        __syncwarp();
    }
}

// ---------------- compat: tiled register-blocked K-GEMM + epilogue ----------------
// Persistent blocks, tile = 128 children x 32 k-cols, 256 threads.
// Main loop: thread computes 4 children x 4 cols (16 FFMA / k-step).
// Epilogue: 2 threads per child; q = gathered qp + RPE-q; compat dot per head;
// __expf; staged vector atomic into segment sums.
__global__ void __launch_bounds__(256, 3) compat_kernel(
    const float* __restrict__ x_child, const float* __restrict__ edge_attr,
    const float* __restrict__ wkv, const float* __restrict__ bkv,
    const float* __restrict__ wk_rpe, const float* __restrict__ bk_rpe,
    const float* __restrict__ wq_rpe, const float* __restrict__ bq_rpe,
    int nc, int ntiles)
{
    __shared__ __align__(16) float ws[64][32];      // k-weights [c][col]
    __shared__ __align__(16) float wkr_s[RPE][32];
    __shared__ __align__(16) float wqr_s[RPE][32];
    __shared__ float bk_s[32], bq_s[32];
    __shared__ __align__(16) float xs[128 * 64];    // x tile; reused as ks[128*33]
    __shared__ __align__(16) float eas[128][12];    // edge_attr (padded 9->12)
    __shared__ __align__(16) float es4[128][4];     // exp(compat) per child/head
    __shared__ int pidx[128];

    const int tid = threadIdx.x;
    const int chgrp = tid & 7;          // col group (cols chgrp*4..+3)
    const int cbase = (tid >> 3) << 2;  // child base (children cbase..+3)

    // one-time weight staging
    for (int k = tid; k < 64 * 32; k += 256) {
        int c = k >> 5, col = k & 31;
        ws[c][col] = wkv[c * KVW + col];
    }
    for (int k = tid; k < RPE * 32; k += 256) {
        int r = k >> 5, col = k & 31;
        wkr_s[r][col] = wk_rpe[k];
        wqr_s[r][col] = wq_rpe[k];
    }
    if (tid < 32) {
        bk_s[tid] = bkv[tid] + bk_rpe[tid];
        bq_s[tid] = bq_rpe[tid];
    }
    __syncthreads();

    float* ks = xs;   // k tile staging, stride 33 (conflict-free)

    for (int tile = blockIdx.x; tile < ntiles; tile += gridDim.x) {
        const int i0 = tile * 128;

        // stage pidx + edge_attr + x tile
        if (tid < 128) {
            int i = i0 + tid;
            pidx[tid] = (i < nc) ? g_idx[i] : 0;
        }
        for (int k = tid; k < 128 * RPE; k += 256) {
            int child = k / RPE, r = k - child * RPE;
            int i = i0 + child;
            eas[child][r] = (i < nc) ? edge_attr[(size_t)i * RPE + r] : 0.f;
        }
#pragma unroll
        for (int k = 0; k < 8; k++) {
            int idx = tid + 256 * k;            // 0..2047
            int child = idx >> 4, c4 = idx & 15;
            int i = i0 + child;
            float4 xv = make_float4(0.f, 0.f, 0.f, 0.f);
            if (i < nc) xv = *(const float4*)&x_child[(size_t)i * DIM + c4 * 4];
            *(float4*)&xs[child * 64 + c4 * 4] = xv;
        }
        __syncthreads();

        // main K-GEMM: 4 children x 4 cols
        float4 a0 = make_float4(0.f, 0.f, 0.f, 0.f);
        float4 a1 = a0, a2 = a0, a3 = a0;
#pragma unroll
        for (int c = 0; c < 64; c++) {
            float4 wv = *(const float4*)&ws[c][chgrp * 4];
            float x0 = xs[(cbase + 0) * 64 + c];
            float x1 = xs[(cbase + 1) * 64 + c];
            float x2 = xs[(cbase + 2) * 64 + c];
            float x3 = xs[(cbase + 3) * 64 + c];
            a0.x += x0 * wv.x; a0.y += x0 * wv.y; a0.z += x0 * wv.z; a0.w += x0 * wv.w;
            a1.x += x1 * wv.x; a1.y += x1 * wv.y; a1.z += x1 * wv.z; a1.w += x1 * wv.w;
            a2.x += x2 * wv.x; a2.y += x2 * wv.y; a2.z += x2 * wv.z; a2.w += x2 * wv.w;
            a3.x += x3 * wv.x; a3.y += x3 * wv.y; a3.z += x3 * wv.z; a3.w += x3 * wv.w;
        }
        // RPE contribution to k
#pragma unroll
        for (int r = 0; r < RPE; r++) {
            float4 wv = *(const float4*)&wkr_s[r][chgrp * 4];
            float e0 = eas[cbase + 0][r];
            float e1 = eas[cbase + 1][r];
            float e2 = eas[cbase + 2][r];
            float e3 = eas[cbase + 3][r];
            a0.x += e0 * wv.x; a0.y += e0 * wv.y; a0.z += e0 * wv.z; a0.w += e0 * wv.w;
            a1.x += e1 * wv.x; a1.y += e1 * wv.y; a1.z += e1 * wv.z; a1.w += e1 * wv.w;
            a2.x += e2 * wv.x; a2.y += e2 * wv.y; a2.z += e2 * wv.z; a2.w += e2 * wv.w;
            a3.x += e3 * wv.x; a3.y += e3 * wv.y; a3.z += e3 * wv.z; a3.w += e3 * wv.w;
        }
        __syncthreads();   // all xs reads done before overwrite with ks

        // write k tile (+bias) into reused buffer, stride 33
        {
            int col = chgrp * 4;
            float b0 = bk_s[col], b1 = bk_s[col + 1], b2 = bk_s[col + 2], b3 = bk_s[col + 3];
            float* k0 = &ks[(cbase + 0) * 33 + col];
            float* k1 = &ks[(cbase + 1) * 33 + col];
            float* k2 = &ks[(cbase + 2) * 33 + col];
            float* k3 = &ks[(cbase + 3) * 33 + col];
            k0[0] = a0.x + b0; k0[1] = a0.y + b1; k0[2] = a0.z + b2; k0[3] = a0.w + b3;
            k1[0] = a1.x + b0; k1[1] = a1.y + b1; k1[2] = a1.z + b2; k1[3] = a1.w + b3;
            k2[0] = a2.x + b0; k2[1] = a2.y + b1; k2[2] = a2.z + b2; k2[3] = a2.w + b3;
            k3[0] = a3.x + b0; k3[1] = a3.y + b1; k3[2] = a3.z + b2; k3[3] = a3.w + b3;
        }
        __syncthreads();

        // epilogue: child = tid>>1, half = tid&1 -> cols [half*16, half*16+16)
        {
            const int child = tid >> 1;
            const int half = tid & 1;
            const int i = i0 + child;
            if (i < nc) {
                const int p = pidx[child];
                const int col0 = half * 16;
                float qreg[16];
                // gathered parent q (already *SCALE, +bq)
                const float4* qpv = (const float4*)&g_qp[(size_t)p * DH + col0];
#pragma unroll
                for (int u = 0; u < 4; u++) {
                    float4 qv = qpv[u];
                    qreg[u * 4 + 0] = qv.x + bq_s[col0 + u * 4 + 0];
                    qreg[u * 4 + 1] = qv.y + bq_s[col0 + u * 4 + 1];
                    qreg[u * 4 + 2] = qv.z + bq_s[col0 + u * 4 + 2];
                    qreg[u * 4 + 3] = qv.w + bq_s[col0 + u * 4 + 3];
                }
#pragma unroll
                for (int r = 0; r < RPE; r++) {
                    float ea = eas[child][r];
#pragma unroll
                    for (int j = 0; j < 16; j++)
                        qreg[j] += ea * wqr_s[r][col0 + j];
                }
                float c0 = 0.f, c1 = 0.f;
#pragma unroll
                for (int j = 0; j < 8; j++)  c0 += qreg[j] * ks[child * 33 + col0 + j];
#pragma unroll
                for (int j = 8; j < 16; j++) c1 += qreg[j] * ks[child * 33 + col0 + j];
                es4[child][half * 2 + 0] = __expf(c0);
                es4[child][half * 2 + 1] = __expf(c1);
            }
        }
        __syncthreads();

        // write e + vector atomic to segment sums
        if (tid < 128) {
            int i = i0 + tid;
            if (i < nc) {
                float4 e4 = *(const float4*)&es4[tid][0];
                *(float4*)&g_e[(size_t)i * H] = e4;
                asm volatile("red.global.add.v4.f32 [%0], {%1,%2,%3,%4};"
                             :: "l"(g_s + (size_t)pidx[tid] * H),
                                "f"(e4.x), "f"(e4.y), "f"(e4.z), "f"(e4.w) : "memory");
            }
        }
        __syncthreads();   // protect shared buffers for next tile
    }
}

// ---------------- segment-sum reciprocal ----------------
__global__ void sinv_kernel(int n) {
    int i = blockIdx.x * blockDim.x + threadIdx.x;
    if (i < n) g_sinv[i] = 1.0f / (g_s[i] + 1e-16f);
}

// ---------------- V projection + scatter (at FFMA roofline) ----------------
__global__ void __launch_bounds__(256, 4) vout_kernel(
    const float* __restrict__ x_child, const float* __restrict__ wkv,
    const float* __restrict__ bkv, float* __restrict__ out,
    int nc, int ntiles)
{
    __shared__ __align__(16) float ws[64][64];
    __shared__ __align__(16) float xs[64][64];
    __shared__ float attn_s[H][64];
    __shared__ int   pidx_s[64];

    const int tid = threadIdx.x;
    const int chgrp = tid & 15;
    const int cbase = (tid >> 4) << 2;
    const int hh = chgrp >> 2;

    for (int k = tid; k < 64 * 64; k += 256) {
        int c = k >> 6, j = k & 63;
        ws[c][j] = wkv[c * KVW + DH + j];
    }
    const float4 bvv = *(const float4*)&bkv[DH + chgrp * 4];
    __syncthreads();

    for (int tile = blockIdx.x; tile < ntiles; tile += gridDim.x) {
        const int i0 = tile * 64;

        {
            int child = tid & 63, h = tid >> 6;
            int i = i0 + child;
            float at = 0.f; int p = 0;
            if (i < nc) {
                p = g_idx[i];
                at = g_e[(size_t)i * H + h] * g_sinv[(size_t)p * H + h];
            }
            attn_s[h][child] = at;
            if (h == 0) pidx_s[child] = p;
        }
#pragma unroll
        for (int k = 0; k < 4; k++) {
            int idx = tid + 256 * k;
            int child = idx >> 4, c4 = idx & 15;
            int i = i0 + child;
            float4 xv = make_float4(0.f, 0.f, 0.f, 0.f);
            if (i < nc) xv = *(const float4*)&x_child[(size_t)i * DIM + c4 * 4];
            *(float4*)&xs[child][c4 * 4] = xv;
        }
        __syncthreads();

        float4 a0 = bvv, a1 = bvv, a2 = bvv, a3 = bvv;
#pragma unroll
        for (int c = 0; c < 64; c++) {
            float4 wv = *(const float4*)&ws[c][chgrp * 4];
            float x0 = xs[cbase + 0][c];
            float x1 = xs[cbase + 1][c];
            float x2 = xs[cbase + 2][c];
            float x3 = xs[cbase + 3][c];
            a0.x += x0 * wv.x; a0.y += x0 * wv.y; a0.z += x0 * wv.z; a0.w += x0 * wv.w;
            a1.x += x1 * wv.x; a1.y += x1 * wv.y; a1.z += x1 * wv.z; a1.w += x1 * wv.w;
            a2.x += x2 * wv.x; a2.y += x2 * wv.y; a2.z += x2 * wv.z; a2.w += x2 * wv.w;
            a3.x += x3 * wv.x; a3.y += x3 * wv.y; a3.z += x3 * wv.z; a3.w += x3 * wv.w;
        }
        __syncthreads();

        {
            float at;
            at = attn_s[hh][cbase + 0];
            a0.x *= at; a0.y *= at; a0.z *= at; a0.w *= at;
            *(float4*)&xs[cbase + 0][chgrp * 4] = a0;
            at = attn_s[hh][cbase + 1];
            a1.x *= at; a1.y *= at; a1.z *= at; a1.w *= at;
            *(float4*)&xs[cbase + 1][chgrp * 4] = a1;
            at = attn_s[hh][cbase + 2];
            a2.x *= at; a2.y *= at; a2.z *= at; a2.w *= at;
            *(float4*)&xs[cbase + 2][chgrp * 4] = a2;
            at = attn_s[hh][cbase + 3];
            a3.x *= at; a3.y *= at; a3.z *= at; a3.w *= at;
            *(float4*)&xs[cbase + 3][chgrp * 4] = a3;
        }
        __syncthreads();

#pragma unroll
        for (int k = 0; k < 4; k++) {
            int idx = tid + 256 * k;
            int child = idx >> 4, grp = idx & 15;
            if (i0 + child < nc) {
                float4 r = *(const float4*)&xs[child][grp * 4];
                asm volatile("red.global.add.v4.f32 [%0], {%1,%2,%3,%4};"
                             :: "l"(out + (size_t)pidx_s[child] * DIM + grp * 4),
                                "f"(r.x), "f"(r.y), "f"(r.z), "f"(r.w) : "memory");
            }
        }
        __syncthreads();
    }
}

// ---------------- launch ----------------
extern "C" void kernel_launch(void* const* d_in, const int* in_sizes, int n_in,
                              void* d_out, int out_size) {
    const float* x_child   = (const float*)d_in[0];
    const float* x_parent  = (const float*)d_in[1];
    const void*  index     = d_in[2];
    const float* edge_attr = (const float*)d_in[3];
    const float* wq        = (const float*)d_in[4];
    const float* bq        = (const float*)d_in[5];
    const float* wkv       = (const float*)d_in[6];
    const float* bkv       = (const float*)d_in[7];
    const float* wk_rpe    = (const float*)d_in[8];
    const float* bk_rpe    = (const float*)d_in[9];
    const float* wq_rpe    = (const float*)d_in[10];
    const float* bq_rpe    = (const float*)d_in[11];
    float* out = (float*)d_out;

    const int nc = in_sizes[0] / DIM;
    const int np = in_sizes[1] / DIM;

    cudaMemsetAsync(d_out, 0, (size_t)out_size * sizeof(float));
    void* s_addr = nullptr;
    cudaGetSymbolAddress(&s_addr, g_s);
    cudaMemsetAsync(s_addr, 0, (size_t)np * H * sizeof(float));

    detect_kernel<<<1, 256>>>((const unsigned int*)index, nc);
    cvt_index_kernel<<<(nc + 255) / 256, 256>>>(index, nc);

    qp_kernel<<<208, 256>>>(x_parent, wq, bq, np);

    const int ctiles = (nc + 127) / 128;
    compat_kernel<<<444, 256>>>(x_child, edge_attr, wkv, bkv,
                                wk_rpe, bk_rpe, wq_rpe, bq_rpe, nc, ctiles);

    sinv_kernel<<<(np * H + 255) / 256, 256>>>(np * H);

    const int ntiles = (nc + 63) / 64;
    vout_kernel<<<592, 256>>>(x_child, wkv, bkv, out, nc, ntiles);
}

// round 4
// speedup vs baseline: 2.9665x; 1.0133x over previous
#include <cuda_runtime.h>
#include <cuda_bf16.h>
#include <cstdint>

#define NC_MAX 1000000
#define NP_MAX 100000
#define DIM 64
#define H 4
#define DQK 8
#define DH 32
#define RPE 9
#define KVW 96
#define SCALE 0.35355339059327373f  // 8^-0.5

// ---------------- packed f32x2 helpers (Blackwell FFMA2 path) ----------------
__device__ __forceinline__ unsigned long long pk2(float v) {
    unsigned long long r;
    asm("mov.b64 %0, {%1, %1};" : "=l"(r) : "f"(v));
    return r;
}
__device__ __forceinline__ void ffma2(unsigned long long& d, unsigned long long a,
                                      unsigned long long b) {
    asm("fma.rn.f32x2 %0, %1, %2, %0;" : "+l"(d) : "l"(a), "l"(b));
}
__device__ __forceinline__ void addf2(unsigned long long& d, unsigned long long a) {
    asm("add.rn.f32x2 %0, %0, %1;" : "+l"(d) : "l"(a));
}
__device__ __forceinline__ void mulf2(unsigned long long& d, unsigned long long a) {
    asm("mul.rn.f32x2 %0, %0, %1;" : "+l"(d) : "l"(a));
}
__device__ __forceinline__ float2 unpk(unsigned long long v) {
    float2 r;
    asm("mov.b64 {%0, %1}, %2;" : "=f"(r.x), "=f"(r.y) : "l"(v));
    return r;
}

// ---------------- device scratch ----------------
__device__ __align__(16) float g_qp[NP_MAX * DH];
__device__ __align__(16) float g_e[NC_MAX * H];
__device__ __align__(16) float g_s[NP_MAX * H];
__device__ __align__(16) float g_sinv[NP_MAX * H];
__device__ int g_idx[NC_MAX];
__device__ int g_is64;

// ---------------- index dtype detection ----------------
__global__ void detect_kernel(const unsigned int* __restrict__ raw, int nc) {
    __shared__ int found;
    if (threadIdx.x == 0) found = 0;
    __syncthreads();
    int limit = nc / 2; if (limit > 2048) limit = 2048;
    for (int i = threadIdx.x; i < limit; i += blockDim.x)
        if (raw[2 * i + 1] != 0u) found = 1;
    __syncthreads();
    if (threadIdx.x == 0) g_is64 = (found == 0) ? 1 : 0;
}

__global__ void cvt_index_kernel(const void* __restrict__ idxp, int nc) {
    int i = blockIdx.x * blockDim.x + threadIdx.x;
    if (i >= nc) return;
    if (g_is64) g_idx[i] = (int)((const long long*)idxp)[i];
    else        g_idx[i] = ((const int*)idxp)[i];
}

// ---------------- parent query projection ----------------
__global__ void __launch_bounds__(256, 2) qp_kernel(
    const float* __restrict__ x_parent, const float* __restrict__ wq,
    const float* __restrict__ bq, int np)
{
    const int t = threadIdx.x & 31;
    const int w = threadIdx.x >> 5;
    __shared__ __align__(16) float xs[8][64];

    float wr[64];
#pragma unroll
    for (int c = 0; c < 64; c++) wr[c] = wq[c * DH + t];
    const float b = bq[t];

    const int warps_total = gridDim.x * 8;
    for (int p = blockIdx.x * 8 + w; p < np; p += warps_total) {
        size_t base = (size_t)p * DIM;
        xs[w][t]      = x_parent[base + t];
        xs[w][t + 32] = x_parent[base + 32 + t];
        __syncwarp();
        float a0 = b, a1 = 0.f, a2 = 0.f, a3 = 0.f;
#pragma unroll
        for (int c = 0; c < 64; c += 4) {
            float4 xv = *(const float4*)&xs[w][c];
            a0 += xv.x * wr[c];
            a1 += xv.y * wr[c + 1];
            a2 += xv.z * wr[c + 2];
            a3 += xv.w * wr[c + 3];
        }
        g_qp[(size_t)p * DH + t] = ((a0 + a1) + (a2 + a3)) * SCALE;
        __syncwarp();
    }
}

// ---------------- compat: FFMA2 K-GEMM + epilogue ----------------
__global__ void __launch_bounds__(256, 3) compat_kernel(
    const float* __restrict__ x_child, const float* __restrict__ edge_attr,
    const float* __restrict__ wkv, const float* __restrict__ bkv,
    const float* __restrict__ wk_rpe, const float* __restrict__ bk_rpe,
    const float* __restrict__ wq_rpe, const float* __restrict__ bq_rpe,
    int nc, int ntiles)
{
    __shared__ __align__(16) float ws[64][32];
    __shared__ __align__(16) float wkr_s[RPE][32];
    __shared__ __align__(16) float wqr_s[RPE][32];
    __shared__ __align__(16) float bk_s[32];
    __shared__ __align__(16) float bq_s[32];
    __shared__ __align__(16) float xs[128 * 64];   // x tile; reused as ks[128*33]
    __shared__ __align__(16) float eas[128][12];
    __shared__ __align__(16) float es4[128][4];
    __shared__ int pidx[128];

    const int tid = threadIdx.x;
    const int chgrp = tid & 7;
    const int cbase = (tid >> 3) << 2;

    for (int k = tid; k < 64 * 32; k += 256) {
        int c = k >> 5, col = k & 31;
        ws[c][col] = wkv[c * KVW + col];
    }
    for (int k = tid; k < RPE * 32; k += 256) {
        wkr_s[0][k] = wk_rpe[k];
        wqr_s[0][k] = wq_rpe[k];
    }
    if (tid < 32) {
        bk_s[tid] = bkv[tid] + bk_rpe[tid];
        bq_s[tid] = bq_rpe[tid];
    }
    __syncthreads();

    float* ks = xs;

    for (int tile = blockIdx.x; tile < ntiles; tile += gridDim.x) {
        const int i0 = tile * 128;

        if (tid < 128) {
            int i = i0 + tid;
            pidx[tid] = (i < nc) ? g_idx[i] : 0;
        }
        for (int k = tid; k < 128 * RPE; k += 256) {
            int child = k / RPE, r = k - child * RPE;
            int i = i0 + child;
            eas[child][r] = (i < nc) ? edge_attr[(size_t)i * RPE + r] : 0.f;
        }
#pragma unroll
        for (int k = 0; k < 8; k++) {
            int idx = tid + 256 * k;
            int child = idx >> 4, c4 = idx & 15;
            int i = i0 + child;
            float4 xv = make_float4(0.f, 0.f, 0.f, 0.f);
            if (i < nc) xv = *(const float4*)&x_child[(size_t)i * DIM + c4 * 4];
            *(float4*)&xs[child * 64 + c4 * 4] = xv;
        }
        __syncthreads();

        // main K-GEMM: 4 children x 4 cols, FFMA2 over column pairs
        unsigned long long acc[4][2] = {{0ull,0ull},{0ull,0ull},{0ull,0ull},{0ull,0ull}};
#pragma unroll
        for (int cc = 0; cc < 64; cc += 4) {
            float4 xv0 = *(const float4*)&xs[(cbase + 0) * 64 + cc];
            float4 xv1 = *(const float4*)&xs[(cbase + 1) * 64 + cc];
            float4 xv2 = *(const float4*)&xs[(cbase + 2) * 64 + cc];
            float4 xv3 = *(const float4*)&xs[(cbase + 3) * 64 + cc];
#pragma unroll
            for (int u = 0; u < 4; u++) {
                ulonglong2 wp = *(const ulonglong2*)&ws[cc + u][chgrp * 4];
                unsigned long long xd;
                xd = pk2(((const float*)&xv0)[u]);
                ffma2(acc[0][0], xd, wp.x); ffma2(acc[0][1], xd, wp.y);
                xd = pk2(((const float*)&xv1)[u]);
                ffma2(acc[1][0], xd, wp.x); ffma2(acc[1][1], xd, wp.y);
                xd = pk2(((const float*)&xv2)[u]);
                ffma2(acc[2][0], xd, wp.x); ffma2(acc[2][1], xd, wp.y);
                xd = pk2(((const float*)&xv3)[u]);
                ffma2(acc[3][0], xd, wp.x); ffma2(acc[3][1], xd, wp.y);
            }
        }
        // RPE contribution to k
#pragma unroll
        for (int r = 0; r < RPE; r++) {
            ulonglong2 wp = *(const ulonglong2*)&wkr_s[r][chgrp * 4];
            unsigned long long xd;
            xd = pk2(eas[cbase + 0][r]);
            ffma2(acc[0][0], xd, wp.x); ffma2(acc[0][1], xd, wp.y);
            xd = pk2(eas[cbase + 1][r]);
            ffma2(acc[1][0], xd, wp.x); ffma2(acc[1][1], xd, wp.y);
            xd = pk2(eas[cbase + 2][r]);
            ffma2(acc[2][0], xd, wp.x); ffma2(acc[2][1], xd, wp.y);
            xd = pk2(eas[cbase + 3][r]);
            ffma2(acc[3][0], xd, wp.x); ffma2(acc[3][1], xd, wp.y);
        }
        __syncthreads();   // xs reads done before overwrite with ks

        // write k tile (+bias), stride 33
        {
            const int col = chgrp * 4;
            const float b0 = bk_s[col], b1 = bk_s[col + 1];
            const float b2 = bk_s[col + 2], b3 = bk_s[col + 3];
#pragma unroll
            for (int i = 0; i < 4; i++) {
                float2 lo = unpk(acc[i][0]);
                float2 hi = unpk(acc[i][1]);
                float* kp = &ks[(cbase + i) * 33 + col];
                kp[0] = lo.x + b0; kp[1] = lo.y + b1;
                kp[2] = hi.x + b2; kp[3] = hi.y + b3;
            }
        }
        __syncthreads();

        // epilogue: 2 threads/child; FFMA2 q-RPE; scalar dot
        {
            const int child = tid >> 1;
            const int half = tid & 1;
            const int i = i0 + child;
            if (i < nc) {
                const int p = pidx[child];
                const int col0 = half * 16;
                unsigned long long q[8];
                const unsigned long long* qpv =
                    (const unsigned long long*)&g_qp[(size_t)p * DH + col0];
                const unsigned long long* bqp =
                    (const unsigned long long*)&bq_s[col0];
#pragma unroll
                for (int j = 0; j < 8; j++) { q[j] = qpv[j]; addf2(q[j], bqp[j]); }
#pragma unroll
                for (int r = 0; r < RPE; r++) {
                    unsigned long long ed = pk2(eas[child][r]);
                    const unsigned long long* wqp =
                        (const unsigned long long*)&wqr_s[r][col0];
#pragma unroll
                    for (int j = 0; j < 8; j++) ffma2(q[j], ed, wqp[j]);
                }
                const float* krow = &ks[child * 33 + col0];
                float c0 = 0.f, c1 = 0.f;
#pragma unroll
                for (int j = 0; j < 4; j++) {
                    float2 qq = unpk(q[j]);
                    c0 += qq.x * krow[2 * j] + qq.y * krow[2 * j + 1];
                }
#pragma unroll
                for (int j = 4; j < 8; j++) {
                    float2 qq = unpk(q[j]);
                    c1 += qq.x * krow[2 * j] + qq.y * krow[2 * j + 1];
                }
                es4[child][half * 2 + 0] = __expf(c0);
                es4[child][half * 2 + 1] = __expf(c1);
            }
        }
        __syncthreads();

        if (tid < 128) {
            int i = i0 + tid;
            if (i < nc) {
                float4 e4 = *(const float4*)&es4[tid][0];
                *(float4*)&g_e[(size_t)i * H] = e4;
                asm volatile("red.global.add.v4.f32 [%0], {%1,%2,%3,%4};"
                             :: "l"(g_s + (size_t)pidx[tid] * H),
                                "f"(e4.x), "f"(e4.y), "f"(e4.z), "f"(e4.w) : "memory");
            }
        }
        __syncthreads();
    }
}

// ---------------- segment-sum reciprocal ----------------
__global__ void sinv_kernel(int n) {
    int i = blockIdx.x * blockDim.x + threadIdx.x;
    if (i < n) g_sinv[i] = 1.0f / (g_s[i] + 1e-16f);
}

// ---------------- V projection + scatter: FFMA2 GEMM ----------------
__global__ void __launch_bounds__(256, 3) vout_kernel(
    const float* __restrict__ x_child, const float* __restrict__ wkv,
    const float* __restrict__ bkv, float* __restrict__ out,
    int nc, int ntiles)
{
    __shared__ __align__(16) float ws[64][64];
    __shared__ __align__(16) float xs[64][64];
    __shared__ float attn_s[H][64];
    __shared__ int   pidx_s[64];

    const int tid = threadIdx.x;
    const int chgrp = tid & 15;
    const int cbase = (tid >> 4) << 2;
    const int hh = chgrp >> 2;

    for (int k = tid; k < 64 * 64; k += 256) {
        int c = k >> 6, j = k & 63;
        ws[c][j] = wkv[c * KVW + DH + j];
    }
    const ulonglong2 bvp = *(const ulonglong2*)&bkv[DH + chgrp * 4];
    __syncthreads();

    for (int tile = blockIdx.x; tile < ntiles; tile += gridDim.x) {
        const int i0 = tile * 64;

        {
            int child = tid & 63, h = tid >> 6;
            int i = i0 + child;
            float at = 0.f; int p = 0;
            if (i < nc) {
                p = g_idx[i];
                at = g_e[(size_t)i * H + h] * g_sinv[(size_t)p * H + h];
            }
            attn_s[h][child] = at;
            if (h == 0) pidx_s[child] = p;
        }
#pragma unroll
        for (int k = 0; k < 4; k++) {
            int idx = tid + 256 * k;
            int child = idx >> 4, c4 = idx & 15;
            int i = i0 + child;
            float4 xv = make_float4(0.f, 0.f, 0.f, 0.f);
            if (i < nc) xv = *(const float4*)&x_child[(size_t)i * DIM + c4 * 4];
            *(float4*)&xs[child][c4 * 4] = xv;
        }
        __syncthreads();

        unsigned long long acc[4][2];
#pragma unroll
        for (int i = 0; i < 4; i++) { acc[i][0] = bvp.x; acc[i][1] = bvp.y; }
#pragma unroll
        for (int cc = 0; cc < 64; cc += 4) {
            float4 xv0 = *(const float4*)&xs[cbase + 0][cc];
            float4 xv1 = *(const float4*)&xs[cbase + 1][cc];
            float4 xv2 = *(const float4*)&xs[cbase + 2][cc];
            float4 xv3 = *(const float4*)&xs[cbase + 3][cc];
#pragma unroll
            for (int u = 0; u < 4; u++) {
                ulonglong2 wp = *(const ulonglong2*)&ws[cc + u][chgrp * 4];
                unsigned long long xd;
                xd = pk2(((const float*)&xv0)[u]);
                ffma2(acc[0][0], xd, wp.x); ffma2(acc[0][1], xd, wp.y);
                xd = pk2(((const float*)&xv1)[u]);
                ffma2(acc[1][0], xd, wp.x); ffma2(acc[1][1], xd, wp.y);
                xd = pk2(((const float*)&xv2)[u]);
                ffma2(acc[2][0], xd, wp.x); ffma2(acc[2][1], xd, wp.y);
                xd = pk2(((const float*)&xv3)[u]);
                ffma2(acc[3][0], xd, wp.x); ffma2(acc[3][1], xd, wp.y);
            }
        }
        __syncthreads();

        // attn scale (packed) + stage into xs
#pragma unroll
        for (int i = 0; i < 4; i++) {
            unsigned long long ad = pk2(attn_s[hh][cbase + i]);
            mulf2(acc[i][0], ad);
            mulf2(acc[i][1], ad);
            ulonglong2 st; st.x = acc[i][0]; st.y = acc[i][1];
            *(ulonglong2*)&xs[cbase + i][chgrp * 4] = st;
        }
        __syncthreads();

#pragma unroll
        for (int k = 0; k < 4; k++) {
            int idx = tid + 256 * k;
            int child = idx >> 4, grp = idx & 15;
            if (i0 + child < nc) {
                float4 r = *(const float4*)&xs[child][grp * 4];
                asm volatile("red.global.add.v4.f32 [%0], {%1,%2,%3,%4};"
                             :: "l"(out + (size_t)pidx_s[child] * DIM + grp * 4),
                                "f"(r.x), "f"(r.y), "f"(r.z), "f"(r.w) : "memory");
            }
        }
        __syncthreads();
    }
}

// ---------------- launch ----------------
extern "C" void kernel_launch(void* const* d_in, const int* in_sizes, int n_in,
                              void* d_out, int out_size) {
    const float* x_child   = (const float*)d_in[0];
    const float* x_parent  = (const float*)d_in[1];
    const void*  index     = d_in[2];
    const float* edge_attr = (const float*)d_in[3];
    const float* wq        = (const float*)d_in[4];
    const float* bq        = (const float*)d_in[5];
    const float* wkv       = (const float*)d_in[6];
    const float* bkv       = (const float*)d_in[7];
    const float* wk_rpe    = (const float*)d_in[8];
    const float* bk_rpe    = (const float*)d_in[9];
    const float* wq_rpe    = (const float*)d_in[10];
    const float* bq_rpe    = (const float*)d_in[11];
    float* out = (float*)d_out;

    const int nc = in_sizes[0] / DIM;
    const int np = in_sizes[1] / DIM;

    cudaMemsetAsync(d_out, 0, (size_t)out_size * sizeof(float));
    void* s_addr = nullptr;
    cudaGetSymbolAddress(&s_addr, g_s);
    cudaMemsetAsync(s_addr, 0, (size_t)np * H * sizeof(float));

    detect_kernel<<<1, 256>>>((const unsigned int*)index, nc);
    cvt_index_kernel<<<(nc + 255) / 256, 256>>>(index, nc);

    qp_kernel<<<208, 256>>>(x_parent, wq, bq, np);

    const int ctiles = (nc + 127) / 128;
    compat_kernel<<<444, 256>>>(x_child, edge_attr, wkv, bkv,
                                wk_rpe, bk_rpe, wq_rpe, bq_rpe, nc, ctiles);

    sinv_kernel<<<(np * H + 255) / 256, 256>>>(np * H);

    const int ntiles = (nc + 63) / 64;
    vout_kernel<<<444, 256>>>(x_child, wkv, bkv, out, nc, ntiles);
}

// round 5
// speedup vs baseline: 3.0575x; 1.0307x over previous
#include <cuda_runtime.h>
#include <cuda_bf16.h>
#include <cstdint>

#define NC_MAX 1000000
#define NP_MAX 100000
#define DIM 64
#define H 4
#define DQK 8
#define DH 32
#define RPE 9
#define KVW 96
#define SCALE 0.35355339059327373f  // 8^-0.5

// ---------------- packed f32x2 helpers ----------------
__device__ __forceinline__ unsigned long long pk2(float v) {
    unsigned long long r;
    asm("mov.b64 %0, {%1, %1};" : "=l"(r) : "f"(v));
    return r;
}
__device__ __forceinline__ void ffma2(unsigned long long& d, unsigned long long a,
                                      unsigned long long b) {
    asm("fma.rn.f32x2 %0, %1, %2, %0;" : "+l"(d) : "l"(a), "l"(b));
}
__device__ __forceinline__ void addf2(unsigned long long& d, unsigned long long a) {
    asm("add.rn.f32x2 %0, %0, %1;" : "+l"(d) : "l"(a));
}
__device__ __forceinline__ void mulf2(unsigned long long& d, unsigned long long a) {
    asm("mul.rn.f32x2 %0, %0, %1;" : "+l"(d) : "l"(a));
}
__device__ __forceinline__ float2 unpk(unsigned long long v) {
    float2 r;
    asm("mov.b64 {%0, %1}, %2;" : "=f"(r.x), "=f"(r.y) : "l"(v));
    return r;
}

// ---------------- device scratch ----------------
__device__ __align__(16) float g_qp[NP_MAX * DH];
__device__ __align__(16) float g_e[NC_MAX * H];
__device__ __align__(16) float g_s[NP_MAX * H];
__device__ __align__(16) float g_sinv[NP_MAX * H];
__device__ int g_idx[NC_MAX];
__device__ int g_is64;

// ---------------- index dtype detection ----------------
__global__ void detect_kernel(const unsigned int* __restrict__ raw, int nc) {
    __shared__ int found;
    if (threadIdx.x == 0) found = 0;
    __syncthreads();
    int limit = nc / 2; if (limit > 2048) limit = 2048;
    for (int i = threadIdx.x; i < limit; i += blockDim.x)
        if (raw[2 * i + 1] != 0u) found = 1;
    __syncthreads();
    if (threadIdx.x == 0) g_is64 = (found == 0) ? 1 : 0;
}

__global__ void cvt_index_kernel(const void* __restrict__ idxp, int nc) {
    int i = blockIdx.x * blockDim.x + threadIdx.x;
    if (i >= nc) return;
    if (g_is64) g_idx[i] = (int)((const long long*)idxp)[i];
    else        g_idx[i] = ((const int*)idxp)[i];
}

// ---------------- parent query projection ----------------
__global__ void __launch_bounds__(256, 2) qp_kernel(
    const float* __restrict__ x_parent, const float* __restrict__ wq,
    const float* __restrict__ bq, int np)
{
    const int t = threadIdx.x & 31;
    const int w = threadIdx.x >> 5;
    __shared__ __align__(16) float xs[8][64];

    float wr[64];
#pragma unroll
    for (int c = 0; c < 64; c++) wr[c] = wq[c * DH + t];
    const float b = bq[t];

    const int warps_total = gridDim.x * 8;
    for (int p = blockIdx.x * 8 + w; p < np; p += warps_total) {
        size_t base = (size_t)p * DIM;
        xs[w][t]      = x_parent[base + t];
        xs[w][t + 32] = x_parent[base + 32 + t];
        __syncwarp();
        float a0 = b, a1 = 0.f, a2 = 0.f, a3 = 0.f;
#pragma unroll
        for (int c = 0; c < 64; c += 4) {
            float4 xv = *(const float4*)&xs[w][c];
            a0 += xv.x * wr[c];
            a1 += xv.y * wr[c + 1];
            a2 += xv.z * wr[c + 2];
            a3 += xv.w * wr[c + 3];
        }
        g_qp[(size_t)p * DH + t] = ((a0 + a1) + (a2 + a3)) * SCALE;
        __syncwarp();
    }
}

// ---------------- compat: 8x4 micro-tile K-GEMM + epilogue ----------------
// tile = 256 children x 32 cols, 256 threads, xs in dynamic smem (64KB)
__global__ void __launch_bounds__(256, 2) compat_kernel(
    const float* __restrict__ x_child, const float* __restrict__ edge_attr,
    const float* __restrict__ wkv, const float* __restrict__ bkv,
    const float* __restrict__ wk_rpe, const float* __restrict__ bk_rpe,
    const float* __restrict__ wq_rpe, const float* __restrict__ bq_rpe,
    int nc, int ntiles)
{
    extern __shared__ __align__(16) float xs[];    // [256*64]; reused as ks[256*33]
    __shared__ __align__(16) float ws[64][32];
    __shared__ __align__(16) float wkr_s[RPE][32];
    __shared__ __align__(16) float wqr_s[RPE][32];
    __shared__ __align__(16) float bk_s[32];
    __shared__ __align__(16) float bq_s[32];
    __shared__ __align__(16) float eas[256][12];
    __shared__ __align__(16) float es4[256][4];
    __shared__ int pidx[256];

    const int tid = threadIdx.x;
    const int cg = tid & 7;            // col group: cols cg*4..+3
    const int chb = (tid >> 3) * 8;    // child base: 8 children

    for (int k = tid; k < 64 * 32; k += 256) {
        int c = k >> 5, col = k & 31;
        ws[c][col] = wkv[c * KVW + col];
    }
    for (int k = tid; k < RPE * 32; k += 256) {
        wkr_s[0][k] = wk_rpe[k];
        wqr_s[0][k] = wq_rpe[k];
    }
    if (tid < 32) {
        bk_s[tid] = bkv[tid] + bk_rpe[tid];
        bq_s[tid] = bq_rpe[tid];
    }
    __syncthreads();

    float* ks = xs;

    for (int tile = blockIdx.x; tile < ntiles; tile += gridDim.x) {
        const int i0 = tile * 256;

        {
            int i = i0 + tid;
            pidx[tid] = (i < nc) ? g_idx[i] : 0;
        }
        for (int k = tid; k < 256 * RPE; k += 256) {
            int child = k / RPE, r = k - child * RPE;
            int i = i0 + child;
            eas[child][r] = (i < nc) ? edge_attr[(size_t)i * RPE + r] : 0.f;
        }
#pragma unroll
        for (int k = 0; k < 16; k++) {
            int idx = tid + 256 * k;           // 0..4095
            int child = idx >> 4, c4 = idx & 15;
            int i = i0 + child;
            float4 xv = make_float4(0.f, 0.f, 0.f, 0.f);
            if (i < nc) xv = *(const float4*)&x_child[(size_t)i * DIM + c4 * 4];
            *(float4*)&xs[child * 64 + c4 * 4] = xv;
        }
        __syncthreads();

        // main K-GEMM: 8 children x 4 cols (FFMA2 over col pairs)
        unsigned long long acc[8][2];
#pragma unroll
        for (int j = 0; j < 8; j++) { acc[j][0] = 0ull; acc[j][1] = 0ull; }
#pragma unroll
        for (int cc = 0; cc < 64; cc += 4) {
            float4 xv[8];
#pragma unroll
            for (int j = 0; j < 8; j++)
                xv[j] = *(const float4*)&xs[(chb + j) * 64 + cc];
#pragma unroll
            for (int u = 0; u < 4; u++) {
                ulonglong2 wp = *(const ulonglong2*)&ws[cc + u][cg * 4];
#pragma unroll
                for (int j = 0; j < 8; j++) {
                    unsigned long long xd = pk2(((const float*)&xv[j])[u]);
                    ffma2(acc[j][0], xd, wp.x);
                    ffma2(acc[j][1], xd, wp.y);
                }
            }
        }
        // RPE contribution to k
#pragma unroll
        for (int r = 0; r < RPE; r++) {
            ulonglong2 wp = *(const ulonglong2*)&wkr_s[r][cg * 4];
#pragma unroll
            for (int j = 0; j < 8; j++) {
                unsigned long long xd = pk2(eas[chb + j][r]);
                ffma2(acc[j][0], xd, wp.x);
                ffma2(acc[j][1], xd, wp.y);
            }
        }
        __syncthreads();   // xs reads done before overwrite with ks

        // write k tile (+bias), stride 33
        {
            const int col = cg * 4;
            const float b0 = bk_s[col], b1 = bk_s[col + 1];
            const float b2 = bk_s[col + 2], b3 = bk_s[col + 3];
#pragma unroll
            for (int j = 0; j < 8; j++) {
                float2 lo = unpk(acc[j][0]);
                float2 hi = unpk(acc[j][1]);
                float* kp = &ks[(chb + j) * 33 + col];
                kp[0] = lo.x + b0; kp[1] = lo.y + b1;
                kp[2] = hi.x + b2; kp[3] = hi.y + b3;
            }
        }
        __syncthreads();

        // epilogue: 512 (child,half) units; thread handles tid and tid+256
#pragma unroll
        for (int uu = 0; uu < 2; uu++) {
            const int unit = tid + uu * 256;
            const int child = unit >> 1;
            const int half = unit & 1;
            const int i = i0 + child;
            if (i < nc) {
                const int p = pidx[child];
                const int col0 = half * 16;
                unsigned long long q[8];
                const unsigned long long* qpv =
                    (const unsigned long long*)&g_qp[(size_t)p * DH + col0];
                const unsigned long long* bqp =
                    (const unsigned long long*)&bq_s[col0];
#pragma unroll
                for (int j = 0; j < 8; j++) { q[j] = qpv[j]; addf2(q[j], bqp[j]); }
#pragma unroll
                for (int r = 0; r < RPE; r++) {
                    unsigned long long ed = pk2(eas[child][r]);
                    const unsigned long long* wqp =
                        (const unsigned long long*)&wqr_s[r][col0];
#pragma unroll
                    for (int j = 0; j < 8; j++) ffma2(q[j], ed, wqp[j]);
                }
                const float* krow = &ks[child * 33 + col0];
                float c0 = 0.f, c1 = 0.f;
#pragma unroll
                for (int j = 0; j < 4; j++) {
                    float2 qq = unpk(q[j]);
                    c0 += qq.x * krow[2 * j] + qq.y * krow[2 * j + 1];
                }
#pragma unroll
                for (int j = 4; j < 8; j++) {
                    float2 qq = unpk(q[j]);
                    c1 += qq.x * krow[2 * j] + qq.y * krow[2 * j + 1];
                }
                es4[child][half * 2 + 0] = __expf(c0);
                es4[child][half * 2 + 1] = __expf(c1);
            }
        }
        __syncthreads();

        {
            int i = i0 + tid;
            if (i < nc) {
                float4 e4 = *(const float4*)&es4[tid][0];
                *(float4*)&g_e[(size_t)i * H] = e4;
                asm volatile("red.global.add.v4.f32 [%0], {%1,%2,%3,%4};"
                             :: "l"(g_s + (size_t)pidx[tid] * H),
                                "f"(e4.x), "f"(e4.y), "f"(e4.z), "f"(e4.w) : "memory");
            }
        }
        __syncthreads();
    }
}

// ---------------- segment-sum reciprocal ----------------
__global__ void sinv_kernel(int n) {
    int i = blockIdx.x * blockDim.x + threadIdx.x;
    if (i < n) g_sinv[i] = 1.0f / (g_s[i] + 1e-16f);
}

// ---------------- vout: 8x8 micro-tile V-GEMM + scatter ----------------
// tile = 256 children x 64 cols, 256 threads, xs in dynamic smem (64KB)
__global__ void __launch_bounds__(256, 2) vout_kernel(
    const float* __restrict__ x_child, const float* __restrict__ wkv,
    const float* __restrict__ bkv, float* __restrict__ out,
    int nc, int ntiles)
{
    extern __shared__ __align__(16) float xs[];    // [256*64]; reused for v staging
    __shared__ __align__(16) float ws[64][64];
    __shared__ __align__(16) float attn_s[256][4];
    __shared__ int pidx[256];

    const int tid = threadIdx.x;
    const int cg = tid & 7;           // cols cg*8..+7 (all within one head)
    const int chb = (tid >> 3) * 8;   // children chb..+7
    const int hh = cg >> 1;           // head of this thread's 8 cols

    for (int k = tid; k < 64 * 64; k += 256) {
        int c = k >> 6, j = k & 63;
        ws[c][j] = wkv[c * KVW + DH + j];
    }
    const ulonglong2 bva = *(const ulonglong2*)&bkv[DH + cg * 8];
    const ulonglong2 bvb = *(const ulonglong2*)&bkv[DH + cg * 8 + 4];
    __syncthreads();

    for (int tile = blockIdx.x; tile < ntiles; tile += gridDim.x) {
        const int i0 = tile * 256;

        // stage attn (coalesced over g_e) + pidx
#pragma unroll
        for (int k = 0; k < 4; k++) {
            int idx = tid + 256 * k;          // 0..1023
            int child = idx >> 2, h = idx & 3;
            int i = i0 + child;
            float at = 0.f; int p = 0;
            if (i < nc) {
                p = g_idx[i];
                at = g_e[(size_t)i * H + h] * g_sinv[(size_t)p * H + h];
            }
            attn_s[child][h] = at;
            if (h == 0) pidx[child] = p;
        }
#pragma unroll
        for (int k = 0; k < 16; k++) {
            int idx = tid + 256 * k;
            int child = idx >> 4, c4 = idx & 15;
            int i = i0 + child;
            float4 xv = make_float4(0.f, 0.f, 0.f, 0.f);
            if (i < nc) xv = *(const float4*)&x_child[(size_t)i * DIM + c4 * 4];
            *(float4*)&xs[child * 64 + c4 * 4] = xv;
        }
        __syncthreads();

        // 8 children x 8 cols micro-tile
        unsigned long long acc[8][4];
#pragma unroll
        for (int j = 0; j < 8; j++) {
            acc[j][0] = bva.x; acc[j][1] = bva.y;
            acc[j][2] = bvb.x; acc[j][3] = bvb.y;
        }
#pragma unroll
        for (int cc = 0; cc < 64; cc += 4) {
            float4 xv[8];
#pragma unroll
            for (int j = 0; j < 8; j++)
                xv[j] = *(const float4*)&xs[(chb + j) * 64 + cc];
#pragma unroll
            for (int u = 0; u < 4; u++) {
                ulonglong2 wpa = *(const ulonglong2*)&ws[cc + u][cg * 8];
                ulonglong2 wpb = *(const ulonglong2*)&ws[cc + u][cg * 8 + 4];
#pragma unroll
                for (int j = 0; j < 8; j++) {
                    unsigned long long xd = pk2(((const float*)&xv[j])[u]);
                    ffma2(acc[j][0], xd, wpa.x);
                    ffma2(acc[j][1], xd, wpa.y);
                    ffma2(acc[j][2], xd, wpb.x);
                    ffma2(acc[j][3], xd, wpb.y);
                }
            }
        }
        __syncthreads();   // xs reads done

        // attn scale + stage v into xs
#pragma unroll
        for (int j = 0; j < 8; j++) {
            unsigned long long ad = pk2(attn_s[chb + j][hh]);
            mulf2(acc[j][0], ad); mulf2(acc[j][1], ad);
            mulf2(acc[j][2], ad); mulf2(acc[j][3], ad);
            ulonglong2 sa; sa.x = acc[j][0]; sa.y = acc[j][1];
            ulonglong2 sb; sb.x = acc[j][2]; sb.y = acc[j][3];
            *(ulonglong2*)&xs[(chb + j) * 64 + cg * 8] = sa;
            *(ulonglong2*)&xs[(chb + j) * 64 + cg * 8 + 4] = sb;
        }
        __syncthreads();

        // scatter
#pragma unroll
        for (int k = 0; k < 16; k++) {
            int idx = tid + 256 * k;
            int child = idx >> 4, grp = idx & 15;
            if (i0 + child < nc) {
                float4 r = *(const float4*)&xs[child * 64 + grp * 4];
                asm volatile("red.global.add.v4.f32 [%0], {%1,%2,%3,%4};"
                             :: "l"(out + (size_t)pidx[child] * DIM + grp * 4),
                                "f"(r.x), "f"(r.y), "f"(r.z), "f"(r.w) : "memory");
            }
        }
        __syncthreads();
    }
}

// ---------------- launch ----------------
extern "C" void kernel_launch(void* const* d_in, const int* in_sizes, int n_in,
                              void* d_out, int out_size) {
    const float* x_child   = (const float*)d_in[0];
    const float* x_parent  = (const float*)d_in[1];
    const void*  index     = d_in[2];
    const float* edge_attr = (const float*)d_in[3];
    const float* wq        = (const float*)d_in[4];
    const float* bq        = (const float*)d_in[5];
    const float* wkv       = (const float*)d_in[6];
    const float* bkv       = (const float*)d_in[7];
    const float* wk_rpe    = (const float*)d_in[8];
    const float* bk_rpe    = (const float*)d_in[9];
    const float* wq_rpe    = (const float*)d_in[10];
    const float* bq_rpe    = (const float*)d_in[11];
    float* out = (float*)d_out;

    const int nc = in_sizes[0] / DIM;
    const int np = in_sizes[1] / DIM;

    const int XS_BYTES = 256 * 64 * (int)sizeof(float);   // 64KB dynamic
    static int attr_done = 0;
    if (!attr_done) {
        cudaFuncSetAttribute(compat_kernel,
                             cudaFuncAttributeMaxDynamicSharedMemorySize, XS_BYTES);
        cudaFuncSetAttribute(vout_kernel,
                             cudaFuncAttributeMaxDynamicSharedMemorySize, XS_BYTES);
        attr_done = 1;
    }

    cudaMemsetAsync(d_out, 0, (size_t)out_size * sizeof(float));
    void* s_addr = nullptr;
    cudaGetSymbolAddress(&s_addr, g_s);
    cudaMemsetAsync(s_addr, 0, (size_t)np * H * sizeof(float));

    detect_kernel<<<1, 256>>>((const unsigned int*)index, nc);
    cvt_index_kernel<<<(nc + 255) / 256, 256>>>(index, nc);

    qp_kernel<<<208, 256>>>(x_parent, wq, bq, np);

    const int ctiles = (nc + 255) / 256;
    compat_kernel<<<296, 256, XS_BYTES>>>(x_child, edge_attr, wkv, bkv,
                                          wk_rpe, bk_rpe, wq_rpe, bq_rpe, nc, ctiles);

    sinv_kernel<<<(np * H + 255) / 256, 256>>>(np * H);

    const int vtiles = (nc + 255) / 256;
    vout_kernel<<<296, 256, XS_BYTES>>>(x_child, wkv, bkv, out, nc, vtiles);
}

// round 6
// speedup vs baseline: 3.2983x; 1.0788x over previous
#include <cuda_runtime.h>
#include <cuda_bf16.h>
#include <cstdint>

#define NC_MAX 1000000
#define NP_MAX 100000
#define DIM 64
#define H 4
#define DQK 8
#define DH 32
#define RPE 9
#define KVW 96
#define SCALE 0.35355339059327373f  // 8^-0.5

// Skewed x-tile index: 16B pad per 8-child group -> conflict-free micro-tile loads
#define XIDX(child, c) (((child) << 6) + (((child) >> 3) << 2) + (c))
#define XS_FLOATS (256 * 64 + 32 * 4)

// ---------------- packed f32x2 helpers ----------------
__device__ __forceinline__ unsigned long long pk2(float v) {
    unsigned long long r;
    asm("mov.b64 %0, {%1, %1};" : "=l"(r) : "f"(v));
    return r;
}
__device__ __forceinline__ void ffma2(unsigned long long& d, unsigned long long a,
                                      unsigned long long b) {
    asm("fma.rn.f32x2 %0, %1, %2, %0;" : "+l"(d) : "l"(a), "l"(b));
}
__device__ __forceinline__ void addf2(unsigned long long& d, unsigned long long a) {
    asm("add.rn.f32x2 %0, %0, %1;" : "+l"(d) : "l"(a));
}
__device__ __forceinline__ void mulf2(unsigned long long& d, unsigned long long a) {
    asm("mul.rn.f32x2 %0, %0, %1;" : "+l"(d) : "l"(a));
}
__device__ __forceinline__ float2 unpk(unsigned long long v) {
    float2 r;
    asm("mov.b64 {%0, %1}, %2;" : "=f"(r.x), "=f"(r.y) : "l"(v));
    return r;
}

// ---------------- device scratch ----------------
__device__ __align__(16) float g_qp[NP_MAX * DH];
__device__ __align__(16) float g_e[NC_MAX * H];
__device__ __align__(16) float g_s[NP_MAX * H];
__device__ __align__(16) float g_sinv[NP_MAX * H];
__device__ int g_idx[NC_MAX];
__device__ int g_is64;

// ---------------- index dtype detection ----------------
__global__ void detect_kernel(const unsigned int* __restrict__ raw, int nc) {
    __shared__ int found;
    if (threadIdx.x == 0) found = 0;
    __syncthreads();
    int limit = nc / 2; if (limit > 2048) limit = 2048;
    for (int i = threadIdx.x; i < limit; i += blockDim.x)
        if (raw[2 * i + 1] != 0u) found = 1;
    __syncthreads();
    if (threadIdx.x == 0) g_is64 = (found == 0) ? 1 : 0;
}

__global__ void cvt_index_kernel(const void* __restrict__ idxp, int nc) {
    int i = blockIdx.x * blockDim.x + threadIdx.x;
    if (i >= nc) return;
    if (g_is64) g_idx[i] = (int)((const long long*)idxp)[i];
    else        g_idx[i] = ((const int*)idxp)[i];
}

// ---------------- parent query projection ----------------
__global__ void __launch_bounds__(256, 2) qp_kernel(
    const float* __restrict__ x_parent, const float* __restrict__ wq,
    const float* __restrict__ bq, int np)
{
    const int t = threadIdx.x & 31;
    const int w = threadIdx.x >> 5;
    __shared__ __align__(16) float xs[8][64];

    float wr[64];
#pragma unroll
    for (int c = 0; c < 64; c++) wr[c] = wq[c * DH + t];
    const float b = bq[t];

    const int warps_total = gridDim.x * 8;
    for (int p = blockIdx.x * 8 + w; p < np; p += warps_total) {
        size_t base = (size_t)p * DIM;
        xs[w][t]      = x_parent[base + t];
        xs[w][t + 32] = x_parent[base + 32 + t];
        __syncwarp();
        float a0 = b, a1 = 0.f, a2 = 0.f, a3 = 0.f;
#pragma unroll
        for (int c = 0; c < 64; c += 4) {
            float4 xv = *(const float4*)&xs[w][c];
            a0 += xv.x * wr[c];
            a1 += xv.y * wr[c + 1];
            a2 += xv.z * wr[c + 2];
            a3 += xv.w * wr[c + 3];
        }
        g_qp[(size_t)p * DH + t] = ((a0 + a1) + (a2 + a3)) * SCALE;
        __syncwarp();
    }
}

// ---------------- compat: 8x4 micro-tile K-GEMM + epilogue ----------------
__global__ void __launch_bounds__(256, 2) compat_kernel(
    const float* __restrict__ x_child, const float* __restrict__ edge_attr,
    const float* __restrict__ wkv, const float* __restrict__ bkv,
    const float* __restrict__ wk_rpe, const float* __restrict__ bk_rpe,
    const float* __restrict__ wq_rpe, const float* __restrict__ bq_rpe,
    int nc, int ntiles)
{
    extern __shared__ __align__(16) float xs[];    // XS_FLOATS; reused as ks[256*33]
    __shared__ __align__(16) float ws[64][32];
    __shared__ __align__(16) float wkr_s[RPE][32];
    __shared__ __align__(16) float wqr_s[RPE][32];
    __shared__ __align__(16) float bk_s[32];
    __shared__ __align__(16) float bq_s[32];
    __shared__ __align__(16) float eas[256][12];
    __shared__ __align__(16) float es4[256][4];
    __shared__ int pidx[256];

    const int tid = threadIdx.x;
    const int cg = tid & 7;            // col group: cols cg*4..+3
    const int chb = (tid >> 3) * 8;    // child base: 8 children

    for (int k = tid; k < 64 * 32; k += 256) {
        int c = k >> 5, col = k & 31;
        ws[c][col] = wkv[c * KVW + col];
    }
    for (int k = tid; k < RPE * 32; k += 256) {
        wkr_s[0][k] = wk_rpe[k];
        wqr_s[0][k] = wq_rpe[k];
    }
    if (tid < 32) {
        bk_s[tid] = bkv[tid] + bk_rpe[tid];
        bq_s[tid] = bq_rpe[tid];
    }
    __syncthreads();

    float* ks = xs;

    for (int tile = blockIdx.x; tile < ntiles; tile += gridDim.x) {
        const int i0 = tile * 256;

        {
            int i = i0 + tid;
            pidx[tid] = (i < nc) ? g_idx[i] : 0;
        }
        for (int k = tid; k < 256 * RPE; k += 256) {
            int child = k / RPE, r = k - child * RPE;
            int i = i0 + child;
            eas[child][r] = (i < nc) ? edge_attr[(size_t)i * RPE + r] : 0.f;
        }
#pragma unroll
        for (int k = 0; k < 16; k++) {
            int idx = tid + 256 * k;           // 0..4095
            int child = idx >> 4, c4 = idx & 15;
            int i = i0 + child;
            float4 xv = make_float4(0.f, 0.f, 0.f, 0.f);
            if (i < nc) xv = *(const float4*)&x_child[(size_t)i * DIM + c4 * 4];
            *(float4*)&xs[XIDX(child, c4 * 4)] = xv;
        }
        __syncthreads();

        // main K-GEMM: 8 children x 4 cols (FFMA2 over col pairs)
        const int xbase = XIDX(chb, 0);
        unsigned long long acc[8][2];
#pragma unroll
        for (int j = 0; j < 8; j++) { acc[j][0] = 0ull; acc[j][1] = 0ull; }
#pragma unroll
        for (int cc = 0; cc < 64; cc += 4) {
            float4 xv[8];
#pragma unroll
            for (int j = 0; j < 8; j++)
                xv[j] = *(const float4*)&xs[xbase + j * 64 + cc];
#pragma unroll
            for (int u = 0; u < 4; u++) {
                ulonglong2 wp = *(const ulonglong2*)&ws[cc + u][cg * 4];
#pragma unroll
                for (int j = 0; j < 8; j++) {
                    unsigned long long xd = pk2(((const float*)&xv[j])[u]);
                    ffma2(acc[j][0], xd, wp.x);
                    ffma2(acc[j][1], xd, wp.y);
                }
            }
        }
        // RPE contribution to k
#pragma unroll
        for (int r = 0; r < RPE; r++) {
            ulonglong2 wp = *(const ulonglong2*)&wkr_s[r][cg * 4];
#pragma unroll
            for (int j = 0; j < 8; j++) {
                unsigned long long xd = pk2(eas[chb + j][r]);
                ffma2(acc[j][0], xd, wp.x);
                ffma2(acc[j][1], xd, wp.y);
            }
        }
        __syncthreads();   // xs reads done before overwrite with ks

        // write k tile (+bias), stride 33
        {
            const int col = cg * 4;
            const float b0 = bk_s[col], b1 = bk_s[col + 1];
            const float b2 = bk_s[col + 2], b3 = bk_s[col + 3];
#pragma unroll
            for (int j = 0; j < 8; j++) {
                float2 lo = unpk(acc[j][0]);
                float2 hi = unpk(acc[j][1]);
                float* kp = &ks[(chb + j) * 33 + col];
                kp[0] = lo.x + b0; kp[1] = lo.y + b1;
                kp[2] = hi.x + b2; kp[3] = hi.y + b3;
            }
        }
        __syncthreads();

        // epilogue: 512 (child,half) units
#pragma unroll
        for (int uu = 0; uu < 2; uu++) {
            const int unit = tid + uu * 256;
            const int child = unit >> 1;
            const int half = unit & 1;
            const int i = i0 + child;
            if (i < nc) {
                const int p = pidx[child];
                const int col0 = half * 16;
                unsigned long long q[8];
                const unsigned long long* qpv =
                    (const unsigned long long*)&g_qp[(size_t)p * DH + col0];
                const unsigned long long* bqp =
                    (const unsigned long long*)&bq_s[col0];
#pragma unroll
                for (int j = 0; j < 8; j++) { q[j] = qpv[j]; addf2(q[j], bqp[j]); }
#pragma unroll
                for (int r = 0; r < RPE; r++) {
                    unsigned long long ed = pk2(eas[child][r]);
                    const unsigned long long* wqp =
                        (const unsigned long long*)&wqr_s[r][col0];
#pragma unroll
                    for (int j = 0; j < 8; j++) ffma2(q[j], ed, wqp[j]);
                }
                const float* krow = &ks[child * 33 + col0];
                float c0 = 0.f, c1 = 0.f;
#pragma unroll
                for (int j = 0; j < 4; j++) {
                    float2 qq = unpk(q[j]);
                    c0 += qq.x * krow[2 * j] + qq.y * krow[2 * j + 1];
                }
#pragma unroll
                for (int j = 4; j < 8; j++) {
                    float2 qq = unpk(q[j]);
                    c1 += qq.x * krow[2 * j] + qq.y * krow[2 * j + 1];
                }
                es4[child][half * 2 + 0] = __expf(c0);
                es4[child][half * 2 + 1] = __expf(c1);
            }
        }
        __syncthreads();

        {
            int i = i0 + tid;
            if (i < nc) {
                float4 e4 = *(const float4*)&es4[tid][0];
                *(float4*)&g_e[(size_t)i * H] = e4;
                asm volatile("red.global.add.v4.f32 [%0], {%1,%2,%3,%4};"
                             :: "l"(g_s + (size_t)pidx[tid] * H),
                                "f"(e4.x), "f"(e4.y), "f"(e4.z), "f"(e4.w) : "memory");
            }
        }
        __syncthreads();
    }
}

// ---------------- segment-sum reciprocal ----------------
__global__ void sinv_kernel(int n) {
    int i = blockIdx.x * blockDim.x + threadIdx.x;
    if (i < n) g_sinv[i] = 1.0f / (g_s[i] + 1e-16f);
}

// ---------------- vout: 8x8 micro-tile V-GEMM + scatter ----------------
__global__ void __launch_bounds__(256, 2) vout_kernel(
    const float* __restrict__ x_child, const float* __restrict__ wkv,
    const float* __restrict__ bkv, float* __restrict__ out,
    int nc, int ntiles)
{
    extern __shared__ __align__(16) float xs[];    // XS_FLOATS; reused for v staging
    __shared__ __align__(16) float ws[64][64];
    __shared__ __align__(16) float attn_s[256][4];
    __shared__ int pidx[256];

    const int tid = threadIdx.x;
    const int cg = tid & 7;           // cols cg*8..+7
    const int chb = (tid >> 3) * 8;   // children chb..+7
    const int hh = cg >> 1;           // head of this thread's 8 cols

    for (int k = tid; k < 64 * 64; k += 256) {
        int c = k >> 6, j = k & 63;
        ws[c][j] = wkv[c * KVW + DH + j];
    }
    const ulonglong2 bva = *(const ulonglong2*)&bkv[DH + cg * 8];
    const ulonglong2 bvb = *(const ulonglong2*)&bkv[DH + cg * 8 + 4];
    __syncthreads();

    for (int tile = blockIdx.x; tile < ntiles; tile += gridDim.x) {
        const int i0 = tile * 256;

#pragma unroll
        for (int k = 0; k < 4; k++) {
            int idx = tid + 256 * k;          // 0..1023
            int child = idx >> 2, h = idx & 3;
            int i = i0 + child;
            float at = 0.f; int p = 0;
            if (i < nc) {
                p = g_idx[i];
                at = g_e[(size_t)i * H + h] * g_sinv[(size_t)p * H + h];
            }
            attn_s[child][h] = at;
            if (h == 0) pidx[child] = p;
        }
#pragma unroll
        for (int k = 0; k < 16; k++) {
            int idx = tid + 256 * k;
            int child = idx >> 4, c4 = idx & 15;
            int i = i0 + child;
            float4 xv = make_float4(0.f, 0.f, 0.f, 0.f);
            if (i < nc) xv = *(const float4*)&x_child[(size_t)i * DIM + c4 * 4];
            *(float4*)&xs[XIDX(child, c4 * 4)] = xv;
        }
        __syncthreads();

        // 8 children x 8 cols micro-tile
        const int xbase = XIDX(chb, 0);
        unsigned long long acc[8][4];
#pragma unroll
        for (int j = 0; j < 8; j++) {
            acc[j][0] = bva.x; acc[j][1] = bva.y;
            acc[j][2] = bvb.x; acc[j][3] = bvb.y;
        }
#pragma unroll
        for (int cc = 0; cc < 64; cc += 4) {
            float4 xv[8];
#pragma unroll
            for (int j = 0; j < 8; j++)
                xv[j] = *(const float4*)&xs[xbase + j * 64 + cc];
#pragma unroll
            for (int u = 0; u < 4; u++) {
                ulonglong2 wpa = *(const ulonglong2*)&ws[cc + u][cg * 8];
                ulonglong2 wpb = *(const ulonglong2*)&ws[cc + u][cg * 8 + 4];
#pragma unroll
                for (int j = 0; j < 8; j++) {
                    unsigned long long xd = pk2(((const float*)&xv[j])[u]);
                    ffma2(acc[j][0], xd, wpa.x);
                    ffma2(acc[j][1], xd, wpa.y);
                    ffma2(acc[j][2], xd, wpb.x);
                    ffma2(acc[j][3], xd, wpb.y);
                }
            }
        }
        __syncthreads();   // xs reads done

        // attn scale + stage v into xs (same skewed layout)
#pragma unroll
        for (int j = 0; j < 8; j++) {
            unsigned long long ad = pk2(attn_s[chb + j][hh]);
            mulf2(acc[j][0], ad); mulf2(acc[j][1], ad);
            mulf2(acc[j][2], ad); mulf2(acc[j][3], ad);
            ulonglong2 sa; sa.x = acc[j][0]; sa.y = acc[j][1];
            ulonglong2 sb; sb.x = acc[j][2]; sb.y = acc[j][3];
            *(ulonglong2*)&xs[xbase + j * 64 + cg * 8] = sa;
            *(ulonglong2*)&xs[xbase + j * 64 + cg * 8 + 4] = sb;
        }
        __syncthreads();

        // scatter
#pragma unroll
        for (int k = 0; k < 16; k++) {
            int idx = tid + 256 * k;
            int child = idx >> 4, grp = idx & 15;
            if (i0 + child < nc) {
                float4 r = *(const float4*)&xs[XIDX(child, grp * 4)];
                asm volatile("red.global.add.v4.f32 [%0], {%1,%2,%3,%4};"
                             :: "l"(out + (size_t)pidx[child] * DIM + grp * 4),
                                "f"(r.x), "f"(r.y), "f"(r.z), "f"(r.w) : "memory");
            }
        }
        __syncthreads();
    }
}

// ---------------- launch ----------------
extern "C" void kernel_launch(void* const* d_in, const int* in_sizes, int n_in,
                              void* d_out, int out_size) {
    const float* x_child   = (const float*)d_in[0];
    const float* x_parent  = (const float*)d_in[1];
    const void*  index     = d_in[2];
    const float* edge_attr = (const float*)d_in[3];
    const float* wq        = (const float*)d_in[4];
    const float* bq        = (const float*)d_in[5];
    const float* wkv       = (const float*)d_in[6];
    const float* bkv       = (const float*)d_in[7];
    const float* wk_rpe    = (const float*)d_in[8];
    const float* bk_rpe    = (const float*)d_in[9];
    const float* wq_rpe    = (const float*)d_in[10];
    const float* bq_rpe    = (const float*)d_in[11];
    float* out = (float*)d_out;

    const int nc = in_sizes[0] / DIM;
    const int np = in_sizes[1] / DIM;

    const int XS_BYTES = XS_FLOATS * (int)sizeof(float);
    static int attr_done = 0;
    if (!attr_done) {
        cudaFuncSetAttribute(compat_kernel,
                             cudaFuncAttributeMaxDynamicSharedMemorySize, XS_BYTES);
        cudaFuncSetAttribute(vout_kernel,
                             cudaFuncAttributeMaxDynamicSharedMemorySize, XS_BYTES);
        attr_done = 1;
    }

    cudaMemsetAsync(d_out, 0, (size_t)out_size * sizeof(float));
    void* s_addr = nullptr;
    cudaGetSymbolAddress(&s_addr, g_s);
    cudaMemsetAsync(s_addr, 0, (size_t)np * H * sizeof(float));

    detect_kernel<<<1, 256>>>((const unsigned int*)index, nc);
    cvt_index_kernel<<<(nc + 255) / 256, 256>>>(index, nc);

    qp_kernel<<<208, 256>>>(x_parent, wq, bq, np);

    const int ctiles = (nc + 255) / 256;
    compat_kernel<<<296, 256, XS_BYTES>>>(x_child, edge_attr, wkv, bkv,
                                          wk_rpe, bk_rpe, wq_rpe, bq_rpe, nc, ctiles);

    sinv_kernel<<<(np * H + 255) / 256, 256>>>(np * H);

    const int vtiles = (nc + 255) / 256;
    vout_kernel<<<296, 256, XS_BYTES>>>(x_child, wkv, bkv, out, nc, vtiles);
}